// round 2
// baseline (speedup 1.0000x reference)
#include <cuda_runtime.h>

// YOLO loss reduction, single-kernel version.
// loss = sum over cells of:
//   (gt[...,4]==1) ? 5*sum((pre[c]-gt[c])^2, c=0..3) + 10*(pre4-gt4)^2
//                  : 0.5*(pre4-gt4)^2
//
// Layout: [B,7,7,30] fp32 -> cells of 30 floats; only channels 0..4 needed.
// Cells are float2-aligned (30 even): stage 3 float2 per cell (floats 0..5)
// per tensor through SMEM with near-coalesced gathers, compute one cell per
// thread from SMEM, accumulate in double, deterministic two-level reduction
// finished by the last-arriving block (wraparound atomicInc -> graph-safe).

#define TPB 256
#define CELLS_PER_TILE 256
#define F2_PER_TILE (CELLS_PER_TILE * 3)   // 768 float2 slots per tensor
#define MAX_BLOCKS 4096

__device__ double g_partials[MAX_BLOCKS];
__device__ unsigned int g_counter = 0;     // wraps back to 0 every launch

__global__ __launch_bounds__(TPB)
void yolo_loss_kernel(const float2* __restrict__ pre2,
                      const float2* __restrict__ gt2,
                      float* __restrict__ out,
                      int ncells, int ntiles) {
    __shared__ float2 sp[F2_PER_TILE];
    __shared__ float2 sg[F2_PER_TILE];
    __shared__ double swarp[TPB / 32];
    __shared__ bool is_last;

    const int tid = threadIdx.x;

    // ---- per-thread staging map: slot i = tid + k*256 -> (cell c, pair r).
    // Constant across tiles; hoisted out of the loop.
    int a[3], c[3];
    #pragma unroll
    for (int k = 0; k < 3; ++k) {
        int i = tid + k * TPB;             // 0..767
        int ck = i / 3;
        int rk = i - 3 * ck;
        c[k] = ck;                         // cell within tile
        a[k] = ck * 15 + rk;               // float2 offset within tile
    }

    double acc = 0.0;

    for (int tile = blockIdx.x; tile < ntiles; tile += gridDim.x) {
        const int cell0 = tile * CELLS_PER_TILE;
        const int base2 = cell0 * 15;      // float2 index of tile start

        // ---- stage floats 0..5 of 256 cells, both tensors
        #pragma unroll
        for (int k = 0; k < 3; ++k) {
            const int i = tid + k * TPB;
            float2 vp = make_float2(0.f, 0.f);
            float2 vg = make_float2(0.f, 0.f);
            if (cell0 + c[k] < ncells) {
                const int off = base2 + a[k];
                vp = __ldg(pre2 + off);
                vg = __ldg(gt2 + off);
            }
            sp[i] = vp;
            sg[i] = vg;
        }
        __syncthreads();

        // ---- one cell per thread
        {
            const int b = tid * 3;
            float2 A0 = sp[b], A1 = sp[b + 1], A2 = sp[b + 2];
            float2 B0 = sg[b], B1 = sg[b + 1], B2 = sg[b + 2];

            float d0 = A0.x - B0.x, d1 = A0.y - B0.y;
            float d2 = A1.x - B1.x, d3 = A1.y - B1.y;
            float coord = fmaf(d0, d0, fmaf(d1, d1, fmaf(d2, d2, d3 * d3)));
            float dc = A2.x - B2.x;
            float conf = dc * dc;

            float cell_loss = (B2.x == 1.0f) ? fmaf(5.0f, coord, 10.0f * conf)
                                             : 0.5f * conf;
            if (cell0 + tid < ncells) acc += (double)cell_loss;
        }
        __syncthreads();
    }

    // ---- block reduction (double) -> one partial per block
    const unsigned full = 0xffffffffu;
    #pragma unroll
    for (int s = 16; s > 0; s >>= 1) acc += __shfl_down_sync(full, acc, s);
    if ((tid & 31) == 0) swarp[tid >> 5] = acc;
    __syncthreads();
    if (tid < 32) {
        double v = (tid < (TPB / 32)) ? swarp[tid] : 0.0;
        #pragma unroll
        for (int s = 16; s > 0; s >>= 1) v += __shfl_down_sync(full, v, s);
        if (tid == 0) g_partials[blockIdx.x] = v;
    }

    // ---- last-arriving block folds the partials (deterministic order)
    if (tid == 0) {
        __threadfence();                                   // publish partial
        unsigned old = atomicInc(&g_counter, gridDim.x - 1);
        is_last = (old == gridDim.x - 1);                  // wraps to 0
    }
    __syncthreads();
    if (is_last) {
        __threadfence();                                   // acquire partials
        double v = 0.0;
        for (int i = tid; i < (int)gridDim.x; i += TPB) v += g_partials[i];
        #pragma unroll
        for (int s = 16; s > 0; s >>= 1) v += __shfl_down_sync(full, v, s);
        if ((tid & 31) == 0) swarp[tid >> 5] = v;
        __syncthreads();
        if (tid < 32) {
            double w = (tid < (TPB / 32)) ? swarp[tid] : 0.0;
            #pragma unroll
            for (int s = 16; s > 0; s >>= 1) w += __shfl_down_sync(full, w, s);
            if (tid == 0) out[0] = (float)w;
        }
    }
}

extern "C" void kernel_launch(void* const* d_in, const int* in_sizes, int n_in,
                              void* d_out, int out_size) {
    const float2* pre2 = (const float2*)d_in[0];
    const float2* gt2  = (const float2*)d_in[1];
    float* out = (float*)d_out;

    const int nelem  = in_sizes[0];
    const int ncells = nelem / 30;
    const int ntiles = (ncells + CELLS_PER_TILE - 1) / CELLS_PER_TILE;

    // 12544 tiles / 1792 blocks = 7 tiles each (even split for this shape).
    int nblocks = ntiles < 1792 ? ntiles : 1792;

    yolo_loss_kernel<<<nblocks, TPB>>>(pre2, gt2, out, ncells, ntiles);
}